// round 11
// baseline (speedup 1.0000x reference)
#include <cuda_runtime.h>

#define T_STEPS 2048
#define BATCH   2048
#define HID     32
#define DF      8
#define DS      24
#define ELEMS_PER_CTA 2   // 2 warps cooperate (j-split) on 2 batch elements

typedef unsigned long long ull;

// ---------- f32x2 packed helpers (sm_100+) ----------
__device__ __forceinline__ ull f2_fma(ull a, ull b, ull c) {
    ull d;
    asm("fma.rn.f32x2 %0, %1, %2, %3;" : "=l"(d) : "l"(a), "l"(b), "l"(c));
    return d;
}
__device__ __forceinline__ ull f2_add(ull a, ull b) {
    ull d;
    asm("add.rn.f32x2 %0, %1, %2;" : "=l"(d) : "l"(a), "l"(b));
    return d;
}
__device__ __forceinline__ void f2_unpack(ull v, float &lo, float &hi) {
    asm("mov.b64 {%0, %1}, %2;" : "=f"(lo), "=f"(hi) : "l"(v));
}

// tanh(x) = sign(x) * (1 - e) / (1 + e), e = exp(-2|x|). ~1e-6 abs error.
__device__ __forceinline__ float fast_tanh(float x) {
    float ax = fabsf(x);
    float e  = __expf(-2.0f * ax);
    float r  = __fdividef(1.0f - e, 1.0f + e);
    return __int_as_float((__float_as_int(x) & 0x80000000) | __float_as_int(r));
}

__device__ __forceinline__ ull lds2(const float* p) {
    return *reinterpret_cast<const ull*>(p);
}

__global__ __launch_bounds__(64)
void chive_kernel(const float* __restrict__ frnn, const float* __restrict__ phrnn,
                  const float* __restrict__ syl,
                  const float* __restrict__ Wx_f, const float* __restrict__ Wh_f,
                  const float* __restrict__ b_f,
                  const float* __restrict__ Wx_p, const float* __restrict__ Wh_p,
                  const float* __restrict__ b_p,
                  const float* __restrict__ Wx_s, const float* __restrict__ Wh_s,
                  const float* __restrict__ b_s,
                  const int* __restrict__ fclk, const int* __restrict__ pclk,
                  const int* __restrict__ sfreq,
                  float* __restrict__ out)
{
    // Merged j-pair weight layout: sW[jp*128 + lane*4 + (j&1)*2 + {0,1}]
    __shared__ __align__(16) float sWA2[20 * 128];  // jp 0-3: (Wx_f,Wx_p); jp 4-19: (Wh_f,Wh_p)
    __shared__ __align__(16) float sWS2[16 * 128];  // (Wx_s, Wh_s) pairs
    __shared__ __align__(16) float sBfp[HID * 2];
    __shared__ __align__(16) float sBs[HID];
    __shared__ unsigned char sFlag[T_STEPS];
    // Per-warp broadcast state (each warp owns + reads its own copy)
    __shared__ __align__(16) float sIn [2][DF * 4];  // (xf0,xp0,xf1,xp1)[j]
    __shared__ __align__(16) float sA  [2][HID * 4]; // (hf0,hp0,hf1,hp1)[j]
    __shared__ __align__(16) float sB0a[2][HID * 4]; // (hf0,hs0_0,hp0,hs1_0)[j]
    __shared__ __align__(16) float sB0b[2][HID * 4]; // (hf1,hs0_1,hp1,hs1_1)[j]
    __shared__ __align__(16) float sB2 [2][HID * 4]; // (xs0,hs2_0,xs1,hs2_1)[j]
    // Double-buffered cross-warp partial-sum exchange
    __shared__ __align__(16) ull sPA [2][2][32][2];
    __shared__ __align__(16) ull sPB0[2][2][32][2];
    __shared__ __align__(16) ull sPB1[2][2][32][2];
    __shared__ __align__(16) ull sPB2[2][2][32][2];

    const int tid = threadIdx.x;

    // ---- prologue: stage weights (merged j-pair layout) + flags ----
    for (int i = tid; i < DF * HID; i += 64) {
        int j = i / HID, l = i % HID;
        int idx = (j >> 1) * 128 + l * 4 + (j & 1) * 2;
        sWA2[idx]     = Wx_f[i];
        sWA2[idx + 1] = Wx_p[i];
    }
    for (int i = tid; i < HID * HID; i += 64) {
        int j = i / HID, l = i % HID;
        int idxA = (4 + (j >> 1)) * 128 + l * 4 + (j & 1) * 2;
        sWA2[idxA]     = Wh_f[i];
        sWA2[idxA + 1] = Wh_p[i];
        int idxS = (j >> 1) * 128 + l * 4 + (j & 1) * 2;
        sWS2[idxS]     = Wx_s[i];
        sWS2[idxS + 1] = Wh_s[i];
    }
    for (int i = tid; i < HID; i += 64) {
        sBfp[2 * i]     = b_f[i];
        sBfp[2 * i + 1] = b_p[i];
        sBs[i]          = b_s[i];
    }
    for (int t = tid; t < T_STEPS; t += 64) {
        unsigned f = 0u;
        if ((t % (fclk[t] + 1)) == 0) f |= 1u;
        if ((t % (pclk[t] + 1)) == 0) f |= 2u;
        if (sfreq[t] == 1)            f |= 4u;
        sFlag[t] = (unsigned char)f;
    }

    const int w    = tid >> 5;     // warp id in CTA (j-split partner index)
    const int wo   = 1 - w;
    const int lane = tid & 31;
    const int b0   = blockIdx.x * ELEMS_PER_CTA;

    float* In_  = sIn[w];
    float* A_   = sA[w];
    float* B0a_ = sB0a[w];
    float* B0b_ = sB0b[w];
    float* B2_  = sB2[w];

    *(float4*)&A_[lane * 4] = make_float4(0.f, 0.f, 0.f, 0.f);
    // CRITICAL: explicit zero-init of B2_. Its xs components (0,2) for
    // j >= DS are NEVER written afterwards (loaders cover j<24 only) and
    // must be the reference's static zero-pad. R5/R9 relied on smem
    // happening to be zero — R9's layout shift exposed the garbage.
    *(float4*)&B2_[lane * 4] = make_float4(0.f, 0.f, 0.f, 0.f);
    __syncthreads();

    // ---- loader roles (identical in both warps; gmem redundant, smem per-warp) ----
    int e = 0, chunk = 0;
    const float* baseP = 0;
    int strideT = 0;
    const bool loader = lane < 20;
    if (lane < 8) {
        e = (lane >> 1) & 1;
        chunk = lane & 1;
        baseP = ((lane < 4) ? frnn : phrnn) + (b0 + e) * DF + chunk * 4;
        strideT = BATCH * DF;
    } else if (lane < 20) {
        int r = lane - 8;
        e = r / 6;
        chunk = r - 6 * e;
        baseP = syl + (b0 + e) * DS + chunk * 4;
        strideT = BATCH * DS;
    }
    const int compA = e * 2 + ((lane >= 4 && lane < 8) ? 1 : 0);
    const int compS = e * 2;
    const int jb    = chunk * 4;

    // register-resident state (neuron = lane); both warps hold full copies
    float hf0 = 0.f, hp0 = 0.f, hs0_0 = 0.f, hs1_0 = 0.f, hs2_0 = 0.f;
    float hf1 = 0.f, hp1 = 0.f, hs0_1 = 0.f, hs1_1 = 0.f, hs2_1 = 0.f;

    const ull   biasfp = lds2(&sBfp[2 * lane]);
    const float bsl    = sBs[lane];

    int abuf = 0, bbuf = 0;

    float4 cur = loader ? *(const float4*)baseP : make_float4(0.f, 0.f, 0.f, 0.f);

    for (int t = 0; t < T_STEPS; t++) {
        float4 nxt = make_float4(0.f, 0.f, 0.f, 0.f);
        if (loader && t + 1 < T_STEPS)
            nxt = *(const float4*)(baseP + (size_t)(t + 1) * strideT);

        const unsigned fl = sFlag[t];

        // ---------------- phase A: f & p cells (j-split across 2 warps) --------------
        if (fl & 3u) {
            if (lane < 8) {
                In_[(jb + 0) * 4 + compA] = cur.x;
                In_[(jb + 1) * 4 + compA] = cur.y;
                In_[(jb + 2) * 4 + compA] = cur.z;
                In_[(jb + 3) * 4 + compA] = cur.w;
            }
            __syncwarp();  // publishes In_ stores AND prev-step A_ publish (intra-warp)

            ull a0A = 0ull, a0B = 0ull, a1A = 0ull, a1B = 0ull;
            #pragma unroll
            for (int jp = 0; jp < 2; jp++) {          // Wx rows: this warp's half
                int jpp = 2 * w + jp;
                ulonglong2 wv = *(const ulonglong2*)&sWA2[jpp * 128 + lane * 4];
                ulonglong2 x0 = *(const ulonglong2*)&In_[(2 * jpp) * 4];
                ulonglong2 x1 = *(const ulonglong2*)&In_[(2 * jpp + 1) * 4];
                a0A = f2_fma(x0.x, wv.x, a0A); a1A = f2_fma(x0.y, wv.x, a1A);
                a0B = f2_fma(x1.x, wv.y, a0B); a1B = f2_fma(x1.y, wv.y, a1B);
            }
            #pragma unroll
            for (int jp = 0; jp < 8; jp++) {          // Wh rows: this warp's half
                int jpp = 8 * w + jp;
                ulonglong2 wv = *(const ulonglong2*)&sWA2[(4 + jpp) * 128 + lane * 4];
                ulonglong2 h0 = *(const ulonglong2*)&A_[(2 * jpp) * 4];
                ulonglong2 h1 = *(const ulonglong2*)&A_[(2 * jpp + 1) * 4];
                a0A = f2_fma(h0.x, wv.x, a0A); a1A = f2_fma(h0.y, wv.x, a1A);
                a0B = f2_fma(h1.x, wv.y, a0B); a1B = f2_fma(h1.y, wv.y, a1B);
            }
            ull pa0 = f2_add(a0A, a0B);
            ull pa1 = f2_add(a1A, a1B);
            sPA[abuf][w][lane][0] = pa0;
            sPA[abuf][w][lane][1] = pa1;
            __syncthreads();
            ulonglong2 o = *(const ulonglong2*)&sPA[abuf][wo][lane][0];
            ull t0 = f2_add(f2_add(pa0, o.x), biasfp);
            ull t1 = f2_add(f2_add(pa1, o.y), biasfp);
            float af0, ap0, af1, ap1;
            f2_unpack(t0, af0, ap0);
            f2_unpack(t1, af1, ap1);
            if (fl & 1u) { hf0 = fast_tanh(af0); hf1 = fast_tanh(af1); }
            if (fl & 2u) { hp0 = fast_tanh(ap0); hp1 = fast_tanh(ap1); }
            *(float4*)&A_[lane * 4] = make_float4(hf0, hp0, hf1, hp1);
            abuf ^= 1;
        }

        // ---------------- phase B: syl cell (3 rows x 2 elems, j-split) --------------
        if (fl & 4u) {
            *(float4*)&B0a_[lane * 4] = make_float4(hf0, hs0_0, hp0, hs1_0);
            *(float4*)&B0b_[lane * 4] = make_float4(hf1, hs0_1, hp1, hs1_1);
            B2_[lane * 4 + 1] = hs2_0;
            B2_[lane * 4 + 3] = hs2_1;
            if (lane >= 8 && lane < 20) {
                B2_[(jb + 0) * 4 + compS] = cur.x;
                B2_[(jb + 1) * 4 + compS] = cur.y;
                B2_[(jb + 2) * 4 + compS] = cur.z;
                B2_[(jb + 3) * 4 + compS] = cur.w;
            }
            __syncwarp();

            ull r00 = 0ull, r10 = 0ull, r20 = 0ull;
            ull r01 = 0ull, r11 = 0ull, r21 = 0ull;
            #pragma unroll
            for (int jp = 0; jp < 8; jp++) {          // this warp's half of rows
                int jpp = 8 * w + jp;
                ulonglong2 wv = *(const ulonglong2*)&sWS2[jpp * 128 + lane * 4];
                ulonglong2 qa0 = *(const ulonglong2*)&B0a_[(2 * jpp) * 4];
                ulonglong2 qb0 = *(const ulonglong2*)&B0b_[(2 * jpp) * 4];
                ulonglong2 qc0 = *(const ulonglong2*)&B2_ [(2 * jpp) * 4];
                r00 = f2_fma(qa0.x, wv.x, r00);
                r10 = f2_fma(qa0.y, wv.x, r10);
                r01 = f2_fma(qb0.x, wv.x, r01);
                r11 = f2_fma(qb0.y, wv.x, r11);
                r20 = f2_fma(qc0.x, wv.x, r20);
                r21 = f2_fma(qc0.y, wv.x, r21);
                ulonglong2 qa1 = *(const ulonglong2*)&B0a_[(2 * jpp + 1) * 4];
                ulonglong2 qb1 = *(const ulonglong2*)&B0b_[(2 * jpp + 1) * 4];
                ulonglong2 qc1 = *(const ulonglong2*)&B2_ [(2 * jpp + 1) * 4];
                r00 = f2_fma(qa1.x, wv.y, r00);
                r10 = f2_fma(qa1.y, wv.y, r10);
                r01 = f2_fma(qb1.x, wv.y, r01);
                r11 = f2_fma(qb1.y, wv.y, r11);
                r20 = f2_fma(qc1.x, wv.y, r20);
                r21 = f2_fma(qc1.y, wv.y, r21);
            }
            sPB0[bbuf][w][lane][0] = r00;
            sPB0[bbuf][w][lane][1] = r10;
            sPB1[bbuf][w][lane][0] = r20;
            sPB1[bbuf][w][lane][1] = r01;
            sPB2[bbuf][w][lane][0] = r11;
            sPB2[bbuf][w][lane][1] = r21;
            __syncthreads();
            ulonglong2 ob0 = *(const ulonglong2*)&sPB0[bbuf][wo][lane][0];
            ulonglong2 ob1 = *(const ulonglong2*)&sPB1[bbuf][wo][lane][0];
            ulonglong2 ob2 = *(const ulonglong2*)&sPB2[bbuf][wo][lane][0];
            float xa, ha;
            f2_unpack(f2_add(r00, ob0.x), xa, ha); hs0_0 = fast_tanh(xa + ha + bsl);
            f2_unpack(f2_add(r10, ob0.y), xa, ha); hs1_0 = fast_tanh(xa + ha + bsl);
            f2_unpack(f2_add(r20, ob1.x), xa, ha); hs2_0 = fast_tanh(xa + ha + bsl);
            f2_unpack(f2_add(r01, ob1.y), xa, ha); hs0_1 = fast_tanh(xa + ha + bsl);
            f2_unpack(f2_add(r11, ob2.x), xa, ha); hs1_1 = fast_tanh(xa + ha + bsl);
            f2_unpack(f2_add(r21, ob2.y), xa, ha); hs2_1 = fast_tanh(xa + ha + bsl);
            bbuf ^= 1;
        }

        cur = nxt;
    }

    // output h_s: [3, B, H] — both warps hold identical results; warp 0 writes
    if (w == 0) {
        out[(0 * BATCH + b0    ) * HID + lane] = hs0_0;
        out[(1 * BATCH + b0    ) * HID + lane] = hs1_0;
        out[(2 * BATCH + b0    ) * HID + lane] = hs2_0;
        out[(0 * BATCH + b0 + 1) * HID + lane] = hs0_1;
        out[(1 * BATCH + b0 + 1) * HID + lane] = hs1_1;
        out[(2 * BATCH + b0 + 1) * HID + lane] = hs2_1;
    }
}

extern "C" void kernel_launch(void* const* d_in, const int* in_sizes, int n_in,
                              void* d_out, int out_size) {
    const float* frnn  = (const float*)d_in[0];
    const float* phrnn = (const float*)d_in[1];
    const float* syl   = (const float*)d_in[2];
    const float* Wx_f  = (const float*)d_in[3];
    const float* Wh_f  = (const float*)d_in[4];
    const float* b_f   = (const float*)d_in[5];
    const float* Wx_p  = (const float*)d_in[6];
    const float* Wh_p  = (const float*)d_in[7];
    const float* b_p   = (const float*)d_in[8];
    const float* Wx_s  = (const float*)d_in[9];
    const float* Wh_s  = (const float*)d_in[10];
    const float* b_s   = (const float*)d_in[11];
    const int*   fclk  = (const int*)d_in[12];
    const int*   pclk  = (const int*)d_in[13];
    const int*   sfreq = (const int*)d_in[14];
    float* out = (float*)d_out;

    dim3 grid(BATCH / ELEMS_PER_CTA);
    dim3 block(64);
    chive_kernel<<<grid, block>>>(frnn, phrnn, syl,
                                  Wx_f, Wh_f, b_f,
                                  Wx_p, Wh_p, b_p,
                                  Wx_s, Wh_s, b_s,
                                  fclk, pclk, sfreq, out);
}

// round 12
// speedup vs baseline: 1.1197x; 1.1197x over previous
#include <cuda_runtime.h>

#define T_STEPS 2048
#define BATCH   2048
#define HID     32
#define DF      8
#define DS      24

typedef unsigned long long ull;

// ---------- f32x2 packed helpers (sm_100+) ----------
__device__ __forceinline__ ull f2_fma(ull a, ull b, ull c) {
    ull d;
    asm("fma.rn.f32x2 %0, %1, %2, %3;" : "=l"(d) : "l"(a), "l"(b), "l"(c));
    return d;
}
__device__ __forceinline__ ull f2_pack(float lo, float hi) {
    ull d;
    asm("mov.b64 %0, {%1, %2};" : "=l"(d) : "f"(lo), "f"(hi));
    return d;
}
__device__ __forceinline__ void f2_unpack(ull v, float &lo, float &hi) {
    asm("mov.b64 {%0, %1}, %2;" : "=f"(lo), "=f"(hi) : "l"(v));
}

// tanh(x) = sign(x) * (1 - e) / (1 + e), e = exp(-2|x|). ~1e-6 abs error.
__device__ __forceinline__ float fast_tanh(float x) {
    float ax = fabsf(x);
    float e  = __expf(-2.0f * ax);
    float r  = __fdividef(1.0f - e, 1.0f + e);
    return __int_as_float((__float_as_int(x) & 0x80000000) | __float_as_int(r));
}

// Pair-state arrays: 4 elements, stride 68 floats (34 pairs) -> 272B, 16B-aligned,
// element offsets land on distinct banks for broadcast reads.
#define ESTRIDE 68

__global__ __launch_bounds__(32)
void chive_kernel(const float* __restrict__ frnn, const float* __restrict__ phrnn,
                  const float* __restrict__ syl,
                  const float* __restrict__ Wx_f, const float* __restrict__ Wh_f,
                  const float* __restrict__ b_f,
                  const float* __restrict__ Wx_p, const float* __restrict__ Wh_p,
                  const float* __restrict__ b_p,
                  const float* __restrict__ Wx_s, const float* __restrict__ Wh_s,
                  const float* __restrict__ b_s,
                  const int* __restrict__ fclk, const int* __restrict__ pclk,
                  const int* __restrict__ sfreq,
                  float* __restrict__ out)
{
    // Weight rows in swizzled quad layout: row j = 64 floats (32 (w0,w1) pairs).
    // Pair (j,l) at: j*64 + ((l>>1)&1)*32 + (l>>2)*4 + (l&1)*2.
    // Lane g reads its 4 pairs as 2 conflict-free LDS.128: [j*64+g*4], [j*64+32+g*4].
    __shared__ __align__(16) float sWA[40 * 64];  // rows 0-7: (Wx_f,Wx_p); 8-39: (Wh_f,Wh_p)
    __shared__ __align__(16) float sWS[32 * 64];  // (Wx_s, Wh_s)
    __shared__ unsigned char sFlag[T_STEPS];
    // Per-element pair-state arrays (one warp per CTA => one copy)
    __shared__ __align__(16) float sPairs[5][4 * ESTRIDE];
    float* sXfp = sPairs[0];   // (xf, xp)[j<8]
    float* sHfp = sPairs[1];   // (hf, hp)[j]
    float* sB0  = sPairs[2];   // (hf, hs0)[j]
    float* sB1  = sPairs[3];   // (hp, hs1)[j]
    float* sB2  = sPairs[4];   // (xs, hs2)[j]  (.x is 0 for j>=24 -- zero-init, g>=6 stores 0)

    const int lane = threadIdx.x;

    // ---- prologue: stage weights (quad layout) + flags ----
    for (int i = lane; i < 40 * 32; i += 32) {
        int j = i >> 5, l = i & 31;
        int off = j * 64 + ((l >> 1) & 1) * 32 + (l >> 2) * 4 + (l & 1) * 2;
        sWA[off]     = (j < 8) ? Wx_f[j * 32 + l] : Wh_f[(j - 8) * 32 + l];
        sWA[off + 1] = (j < 8) ? Wx_p[j * 32 + l] : Wh_p[(j - 8) * 32 + l];
        if (j < 32) {
            sWS[off]     = Wx_s[j * 32 + l];
            sWS[off + 1] = Wh_s[j * 32 + l];
        }
    }
    for (int t = lane; t < T_STEPS; t += 32) {
        unsigned f = 0u;
        if ((t % (fclk[t] + 1)) == 0) f |= 1u;
        if ((t % (pclk[t] + 1)) == 0) f |= 2u;
        if (sfreq[t] == 1)            f |= 4u;
        sFlag[t] = (unsigned char)f;
    }
    for (int i = lane; i < 5 * 4 * ESTRIDE; i += 32)
        ((float*)sPairs)[i] = 0.f;   // h0 = 0 AND the permanent x_s zero-pad (j>=24)
    __syncwarp();

    const int e  = lane >> 3;        // element index within warp (0..3)
    const int g  = lane & 7;         // output-group: lane owns l = 4g..4g+3
    const int g4 = g * 4;            // float offset of this lane's weight quad
    const int eoff = e * ESTRIDE;
    const int b0 = blockIdx.x * 4;
    const int bidx = b0 + e;

    // register state: this lane's 4 outputs per network, for its element
    float hf[4]  = {0.f, 0.f, 0.f, 0.f};
    float hp[4]  = {0.f, 0.f, 0.f, 0.f};
    float hs0[4] = {0.f, 0.f, 0.f, 0.f};
    float hs1[4] = {0.f, 0.f, 0.f, 0.f};
    float hs2[4] = {0.f, 0.f, 0.f, 0.f};

    // biases (gmem, one-time)
    ull  biasq[4];
    float bs[4];
    #pragma unroll
    for (int i = 0; i < 4; i++) {
        biasq[i] = f2_pack(b_f[g4 + i], b_p[g4 + i]);
        bs[i]    = b_s[g4 + i];
    }

    // ---- loader roles ----
    // g < 6 : xs loader (owner lane loads its own 4 syl floats)
    // g = 6 : frnn+phrnn j=0..3 ; g = 7 : frnn+phrnn j=4..7
    float4 xs_c = make_float4(0.f, 0.f, 0.f, 0.f);
    float4 xf_c = xs_c, xp_c = xs_c;
    {
        if (g < 6) {
            xs_c = *(const float4*)(syl + ((size_t)0 * BATCH + bidx) * DS + g4);
        } else {
            size_t base = ((size_t)0 * BATCH + bidx) * DF + (g - 6) * 4;
            xf_c = *(const float4*)(frnn  + base);
            xp_c = *(const float4*)(phrnn + base);
        }
    }

    for (int t = 0; t < T_STEPS; t++) {
        // prefetch next step's inputs
        float4 xs_n = make_float4(0.f, 0.f, 0.f, 0.f);
        float4 xf_n = xs_n, xp_n = xs_n;
        if (t + 1 < T_STEPS) {
            if (g < 6) {
                xs_n = *(const float4*)(syl + ((size_t)(t + 1) * BATCH + bidx) * DS + g4);
            } else {
                size_t base = ((size_t)(t + 1) * BATCH + bidx) * DF + (g - 6) * 4;
                xf_n = *(const float4*)(frnn  + base);
                xp_n = *(const float4*)(phrnn + base);
            }
        }

        const unsigned fl = sFlag[t];

        // ================= phase A: f & p cells =================
        if (fl & 3u) {
            if (g >= 6) {
                int jb = (g - 6) * 8;  // float offset of pair j=(g-6)*4
                *(ull*)&sXfp[eoff + jb + 0] = f2_pack(xf_c.x, xp_c.x);
                *(ull*)&sXfp[eoff + jb + 2] = f2_pack(xf_c.y, xp_c.y);
                *(ull*)&sXfp[eoff + jb + 4] = f2_pack(xf_c.z, xp_c.z);
                *(ull*)&sXfp[eoff + jb + 6] = f2_pack(xf_c.w, xp_c.w);
            }
            __syncwarp();

            ull a0 = biasq[0], a1 = biasq[1], a2 = biasq[2], a3 = biasq[3];
            #pragma unroll
            for (int j = 0; j < DF; j++) {
                const float* wrow = &sWA[j * 64 + g4];
                ulonglong2 w0 = *(const ulonglong2*)wrow;
                ulonglong2 w1 = *(const ulonglong2*)(wrow + 32);
                ull op = *(const ull*)&sXfp[eoff + 2 * j];
                a0 = f2_fma(op, w0.x, a0); a1 = f2_fma(op, w0.y, a1);
                a2 = f2_fma(op, w1.x, a2); a3 = f2_fma(op, w1.y, a3);
            }
            #pragma unroll
            for (int j = 0; j < HID; j++) {
                const float* wrow = &sWA[(DF + j) * 64 + g4];
                ulonglong2 w0 = *(const ulonglong2*)wrow;
                ulonglong2 w1 = *(const ulonglong2*)(wrow + 32);
                ull op = *(const ull*)&sHfp[eoff + 2 * j];
                a0 = f2_fma(op, w0.x, a0); a1 = f2_fma(op, w0.y, a1);
                a2 = f2_fma(op, w1.x, a2); a3 = f2_fma(op, w1.y, a3);
            }
            __syncwarp();   // all lanes finished reading old sHfp

            float af[4], ap[4];
            f2_unpack(a0, af[0], ap[0]);
            f2_unpack(a1, af[1], ap[1]);
            f2_unpack(a2, af[2], ap[2]);
            f2_unpack(a3, af[3], ap[3]);
            if (fl & 1u) {
                #pragma unroll
                for (int i = 0; i < 4; i++) hf[i] = fast_tanh(af[i]);
            }
            if (fl & 2u) {
                #pragma unroll
                for (int i = 0; i < 4; i++) hp[i] = fast_tanh(ap[i]);
            }
            *(float4*)&sHfp[eoff + 8 * g]     = make_float4(hf[0], hp[0], hf[1], hp[1]);
            *(float4*)&sHfp[eoff + 8 * g + 4] = make_float4(hf[2], hp[2], hf[3], hp[3]);
        }

        // ================= phase B: syl cell (3 rows) =================
        if (fl & 4u) {
            __syncwarp();   // previous B matvec reads complete before overwrite
            // owner lanes publish operand pairs from registers (+ fresh xs input)
            *(float4*)&sB0[eoff + 8 * g]     = make_float4(hf[0], hs0[0], hf[1], hs0[1]);
            *(float4*)&sB0[eoff + 8 * g + 4] = make_float4(hf[2], hs0[2], hf[3], hs0[3]);
            *(float4*)&sB1[eoff + 8 * g]     = make_float4(hp[0], hs1[0], hp[1], hs1[1]);
            *(float4*)&sB1[eoff + 8 * g + 4] = make_float4(hp[2], hs1[2], hp[3], hs1[3]);
            // xs_c stays zero for g>=6 (never loaded) == reference zero-pad
            *(float4*)&sB2[eoff + 8 * g]     = make_float4(xs_c.x, hs2[0], xs_c.y, hs2[1]);
            *(float4*)&sB2[eoff + 8 * g + 4] = make_float4(xs_c.z, hs2[2], xs_c.w, hs2[3]);
            __syncwarp();

            ull r[12];
            #pragma unroll
            for (int i = 0; i < 4; i++) {
                ull b = f2_pack(bs[i], 0.f);
                r[i] = b; r[4 + i] = b; r[8 + i] = b;
            }
            #pragma unroll
            for (int j = 0; j < HID; j++) {
                const float* wrow = &sWS[j * 64 + g4];
                ulonglong2 w0 = *(const ulonglong2*)wrow;
                ulonglong2 w1 = *(const ulonglong2*)(wrow + 32);
                ull q0 = *(const ull*)&sB0[eoff + 2 * j];
                ull q1 = *(const ull*)&sB1[eoff + 2 * j];
                ull q2 = *(const ull*)&sB2[eoff + 2 * j];
                r[0]  = f2_fma(q0, w0.x, r[0]);  r[1]  = f2_fma(q0, w0.y, r[1]);
                r[2]  = f2_fma(q0, w1.x, r[2]);  r[3]  = f2_fma(q0, w1.y, r[3]);
                r[4]  = f2_fma(q1, w0.x, r[4]);  r[5]  = f2_fma(q1, w0.y, r[5]);
                r[6]  = f2_fma(q1, w1.x, r[6]);  r[7]  = f2_fma(q1, w1.y, r[7]);
                r[8]  = f2_fma(q2, w0.x, r[8]);  r[9]  = f2_fma(q2, w0.y, r[9]);
                r[10] = f2_fma(q2, w1.x, r[10]); r[11] = f2_fma(q2, w1.y, r[11]);
            }
            #pragma unroll
            for (int i = 0; i < 4; i++) {
                float xa, ha;
                f2_unpack(r[i],     xa, ha); hs0[i] = fast_tanh(xa + ha);
                f2_unpack(r[4 + i], xa, ha); hs1[i] = fast_tanh(xa + ha);
                f2_unpack(r[8 + i], xa, ha); hs2[i] = fast_tanh(xa + ha);
            }
        }

        xs_c = xs_n; xf_c = xf_n; xp_c = xp_n;
    }

    // output h_s: [3, B, H]; lane owns l = 4g..4g+3 of element bidx
    *(float4*)&out[(0 * BATCH + bidx) * HID + g4] = make_float4(hs0[0], hs0[1], hs0[2], hs0[3]);
    *(float4*)&out[(1 * BATCH + bidx) * HID + g4] = make_float4(hs1[0], hs1[1], hs1[2], hs1[3]);
    *(float4*)&out[(2 * BATCH + bidx) * HID + g4] = make_float4(hs2[0], hs2[1], hs2[2], hs2[3]);
}

extern "C" void kernel_launch(void* const* d_in, const int* in_sizes, int n_in,
                              void* d_out, int out_size) {
    const float* frnn  = (const float*)d_in[0];
    const float* phrnn = (const float*)d_in[1];
    const float* syl   = (const float*)d_in[2];
    const float* Wx_f  = (const float*)d_in[3];
    const float* Wh_f  = (const float*)d_in[4];
    const float* b_f   = (const float*)d_in[5];
    const float* Wx_p  = (const float*)d_in[6];
    const float* Wh_p  = (const float*)d_in[7];
    const float* b_p   = (const float*)d_in[8];
    const float* Wx_s  = (const float*)d_in[9];
    const float* Wh_s  = (const float*)d_in[10];
    const float* b_s   = (const float*)d_in[11];
    const int*   fclk  = (const int*)d_in[12];
    const int*   pclk  = (const int*)d_in[13];
    const int*   sfreq = (const int*)d_in[14];
    float* out = (float*)d_out;

    dim3 grid(BATCH / 4);
    dim3 block(32);
    chive_kernel<<<grid, block>>>(frnn, phrnn, syl,
                                  Wx_f, Wh_f, b_f,
                                  Wx_p, Wh_p, b_p,
                                  Wx_s, Wh_s, b_s,
                                  fclk, pclk, sfreq, out);
}

// round 13
// speedup vs baseline: 1.3352x; 1.1925x over previous
#include <cuda_runtime.h>

#define T_STEPS 2048
#define BATCH   2048
#define HID     32
#define DF      8
#define DS      24
#define ESTR2   68    // floats per element, pair arrays (272B; e-offsets hit distinct banks)
#define ESTR4   132   // floats per element, float4 array (528B; 528%128=16 -> distinct banks)

typedef unsigned long long ull;

__device__ __forceinline__ ull f2_fma(ull a, ull b, ull c) {
    ull d;
    asm("fma.rn.f32x2 %0, %1, %2, %3;" : "=l"(d) : "l"(a), "l"(b), "l"(c));
    return d;
}
__device__ __forceinline__ ull f2_add(ull a, ull b) {
    ull d;
    asm("add.rn.f32x2 %0, %1, %2;" : "=l"(d) : "l"(a), "l"(b));
    return d;
}
__device__ __forceinline__ ull f2_pack(float lo, float hi) {
    ull d;
    asm("mov.b64 %0, {%1, %2};" : "=l"(d) : "f"(lo), "f"(hi));
    return d;
}
__device__ __forceinline__ void f2_unpack(ull v, float &lo, float &hi) {
    asm("mov.b64 {%0, %1}, %2;" : "=f"(lo), "=f"(hi) : "l"(v));
}

// tanh(x) = sign(x) * (1 - e) / (1 + e), e = exp(-2|x|). ~1e-6 abs error.
__device__ __forceinline__ float fast_tanh(float x) {
    float ax = fabsf(x);
    float e  = __expf(-2.0f * ax);
    float r  = __fdividef(1.0f - e, 1.0f + e);
    return __int_as_float((__float_as_int(x) & 0x80000000) | __float_as_int(r));
}

__global__ __launch_bounds__(64)
void chive_kernel(const float* __restrict__ frnn, const float* __restrict__ phrnn,
                  const float* __restrict__ syl,
                  const float* __restrict__ Wx_f, const float* __restrict__ Wh_f,
                  const float* __restrict__ b_f,
                  const float* __restrict__ Wx_p, const float* __restrict__ Wh_p,
                  const float* __restrict__ b_p,
                  const float* __restrict__ Wx_s, const float* __restrict__ Wh_s,
                  const float* __restrict__ b_s,
                  const int* __restrict__ fclk, const int* __restrict__ pclk,
                  const int* __restrict__ sfreq,
                  float* __restrict__ out)
{
    // Weight rows: row j = 64 floats; warp-half at j*64 + w*32; lane quad (2 pairs)
    // at + g*4. Lane g reads LDS.128 -> 8 distinct 16B in a 128B block = 1 phase.
    __shared__ __align__(16) float sWA[40 * 64];  // rows 0-7: (Wx_f,Wx_p); 8-39: (Wh_f,Wh_p)
    __shared__ __align__(16) float sWS[32 * 64];  // (Wx_s, Wh_s)
    __shared__ unsigned char sFlag[T_STEPS];
    // Double-buffered per-element state (4 elements per CTA)
    __shared__ __align__(16) float sX  [2][4 * ESTR2];  // (xf,xp)[j<8]
    __shared__ __align__(16) float sH  [2][4 * ESTR2];  // (hf,hp)[j]
    __shared__ __align__(16) float sB01[2][4 * ESTR4];  // (hf,hs0,hp,hs1)[j]
    __shared__ __align__(16) float sB2 [2][4 * ESTR2];  // (xs,hs2)[j]

    const int tid = threadIdx.x;

    // ---- prologue ----
    for (int i = tid; i < 40 * 32; i += 64) {
        int j = i >> 5, l = i & 31;
        int off = j * 64 + (l >> 4) * 32 + ((l & 15) >> 1) * 4 + (l & 1) * 2;
        sWA[off]     = (j < 8) ? Wx_f[j * 32 + l] : Wh_f[(j - 8) * 32 + l];
        sWA[off + 1] = (j < 8) ? Wx_p[j * 32 + l] : Wh_p[(j - 8) * 32 + l];
        if (j < 32) {
            sWS[off]     = Wx_s[j * 32 + l];
            sWS[off + 1] = Wh_s[j * 32 + l];
        }
    }
    for (int t = tid; t < T_STEPS; t += 64) {
        unsigned f = 0u;
        if ((t % (fclk[t] + 1)) == 0) f |= 1u;
        if ((t % (pclk[t] + 1)) == 0) f |= 2u;
        if (sfreq[t] == 1)            f |= 4u;
        sFlag[t] = (unsigned char)f;
    }
    for (int i = tid; i < 2 * 4 * ESTR2; i += 64) {
        ((float*)sX)[i]  = 0.f;
        ((float*)sH)[i]  = 0.f;
        ((float*)sB2)[i] = 0.f;
    }
    for (int i = tid; i < 2 * 4 * ESTR4; i += 64)
        ((float*)sB01)[i] = 0.f;
    __syncthreads();

    const int w    = tid >> 5;        // warp: owns neurons [16w, 16w+16)
    const int lane = tid & 31;
    const int e    = lane >> 3;       // element 0..3
    const int g    = lane & 7;
    const int l0   = w * 16 + g * 2;  // this lane's 2 neurons: l0, l0+1
    const int bidx = blockIdx.x * 4 + e;
    const int eoff2 = e * ESTR2;
    const int eoff4 = e * ESTR4;

    // register state for this lane's 2 neurons
    float hf[2]  = {0.f, 0.f}, hp[2]  = {0.f, 0.f};
    float hs0[2] = {0.f, 0.f}, hs1[2] = {0.f, 0.f}, hs2[2] = {0.f, 0.f};

    ull  biasq[2];
    float bs[2];
    #pragma unroll
    for (int i = 0; i < 2; i++) {
        biasq[i] = f2_pack(b_f[l0 + i], b_p[l0 + i]);
        bs[i]    = b_s[l0 + i];
    }

    // loader roles
    const bool xfp_loader = (w == 0 && g < 4);          // pairs j = 2g, 2g+1
    const bool xs_loader  = (l0 < DS);                  // l0 even; l0<=22 => both < 24
    const float* fP = frnn  + (size_t)bidx * DF + g * 2;
    const float* pP = phrnn + (size_t)bidx * DF + g * 2;
    const float* sP = syl   + (size_t)bidx * DS + l0;

    float2 xf_c = make_float2(0.f, 0.f), xp_c = xf_c, xs_c = xf_c;
    if (xfp_loader) { xf_c = *(const float2*)fP; xp_c = *(const float2*)pP; }
    if (xs_loader)  { xs_c = *(const float2*)sP; }

    int pa = 0, qx = 0, qb = 0;

    for (int t = 0; t < T_STEPS; t++) {
        float2 xf_n = make_float2(0.f, 0.f), xp_n = xf_n, xs_n = xf_n;
        if (t + 1 < T_STEPS) {
            size_t so = (size_t)(t + 1) * BATCH;
            if (xfp_loader) {
                xf_n = *(const float2*)(fP + so * DF);
                xp_n = *(const float2*)(pP + so * DF);
            }
            if (xs_loader) xs_n = *(const float2*)(sP + so * DS);
        }

        const unsigned fl = sFlag[t];

        // ================= phase A: f & p cells =================
        if (fl & 3u) {
            qx ^= 1;
            if (xfp_loader)  // pairs (2g,2g+1): (xf0,xp0,xf1,xp1) STS.128
                *(float4*)&sX[qx][eoff2 + g * 4] =
                    make_float4(xf_c.x, xp_c.x, xf_c.y, xp_c.y);
            __syncthreads();   // publish x; h(pa) already visible (stored before prior bar's phase end)

            ull a0A = biasq[0], a0B = 0ull, a1A = biasq[1], a1B = 0ull;
            #pragma unroll
            for (int j = 0; j < DF; j++) {
                ulonglong2 wv = *(const ulonglong2*)&sWA[j * 64 + w * 32 + g * 4];
                ull op = *(const ull*)&sX[qx][eoff2 + 2 * j];
                if (j & 1) { a0B = f2_fma(op, wv.x, a0B); a1B = f2_fma(op, wv.y, a1B); }
                else       { a0A = f2_fma(op, wv.x, a0A); a1A = f2_fma(op, wv.y, a1A); }
            }
            #pragma unroll
            for (int j = 0; j < HID; j++) {
                ulonglong2 wv = *(const ulonglong2*)&sWA[(DF + j) * 64 + w * 32 + g * 4];
                ull op = *(const ull*)&sH[pa][eoff2 + 2 * j];
                if (j & 1) { a0B = f2_fma(op, wv.x, a0B); a1B = f2_fma(op, wv.y, a1B); }
                else       { a0A = f2_fma(op, wv.x, a0A); a1A = f2_fma(op, wv.y, a1A); }
            }
            float af[2], ap[2];
            f2_unpack(f2_add(a0A, a0B), af[0], ap[0]);
            f2_unpack(f2_add(a1A, a1B), af[1], ap[1]);
            if (fl & 1u) { hf[0] = fast_tanh(af[0]); hf[1] = fast_tanh(af[1]); }
            if (fl & 2u) { hp[0] = fast_tanh(ap[0]); hp[1] = fast_tanh(ap[1]); }
            // write NEW buffer (pa^1): WAR-safe (prior readers finished before this bar)
            *(float4*)&sH[pa ^ 1][eoff2 + l0 * 2] =
                make_float4(hf[0], hp[0], hf[1], hp[1]);
            pa ^= 1;
        }

        // ================= phase B: syl cell (3 rows) =================
        if (fl & 4u) {
            qb ^= 1;
            // republish operands from registers (B never reads sH)
            *(float4*)&sB01[qb][eoff4 + l0 * 4] =
                make_float4(hf[0], hs0[0], hp[0], hs1[0]);
            *(float4*)&sB01[qb][eoff4 + l0 * 4 + 4] =
                make_float4(hf[1], hs0[1], hp[1], hs1[1]);
            *(float4*)&sB2[qb][eoff2 + l0 * 2] =
                make_float4(xs_c.x, hs2[0], xs_c.y, hs2[1]);  // xs=0 for l0>=24 (never loaded)
            __syncthreads();

            ull r00 = 0ull, r01 = 0ull, r02 = 0ull;
            ull r10 = 0ull, r11 = 0ull, r12 = 0ull;
            #pragma unroll
            for (int j = 0; j < HID; j++) {
                ulonglong2 wv  = *(const ulonglong2*)&sWS[j * 64 + w * 32 + g * 4];
                ulonglong2 q01 = *(const ulonglong2*)&sB01[qb][eoff4 + j * 4];
                ull q2 = *(const ull*)&sB2[qb][eoff2 + 2 * j];
                r00 = f2_fma(q01.x, wv.x, r00);  // (hf*Wx, hs0*Wh) -> row0 neuron0
                r01 = f2_fma(q01.y, wv.x, r01);  // (hp*Wx, hs1*Wh) -> row1 neuron0
                r02 = f2_fma(q2,    wv.x, r02);  // (xs*Wx, hs2*Wh) -> row2 neuron0
                r10 = f2_fma(q01.x, wv.y, r10);
                r11 = f2_fma(q01.y, wv.y, r11);
                r12 = f2_fma(q2,    wv.y, r12);
            }
            float xa, ha;
            f2_unpack(r00, xa, ha); hs0[0] = fast_tanh(xa + ha + bs[0]);
            f2_unpack(r01, xa, ha); hs1[0] = fast_tanh(xa + ha + bs[0]);
            f2_unpack(r02, xa, ha); hs2[0] = fast_tanh(xa + ha + bs[0]);
            f2_unpack(r10, xa, ha); hs0[1] = fast_tanh(xa + ha + bs[1]);
            f2_unpack(r11, xa, ha); hs1[1] = fast_tanh(xa + ha + bs[1]);
            f2_unpack(r12, xa, ha); hs2[1] = fast_tanh(xa + ha + bs[1]);
        }

        xf_c = xf_n; xp_c = xp_n; xs_c = xs_n;
    }

    // output h_s: [3, B, H]; lane owns neurons l0, l0+1 of element bidx
    *(float2*)&out[(0 * BATCH + bidx) * HID + l0] = make_float2(hs0[0], hs0[1]);
    *(float2*)&out[(1 * BATCH + bidx) * HID + l0] = make_float2(hs1[0], hs1[1]);
    *(float2*)&out[(2 * BATCH + bidx) * HID + l0] = make_float2(hs2[0], hs2[1]);
}

extern "C" void kernel_launch(void* const* d_in, const int* in_sizes, int n_in,
                              void* d_out, int out_size) {
    const float* frnn  = (const float*)d_in[0];
    const float* phrnn = (const float*)d_in[1];
    const float* syl   = (const float*)d_in[2];
    const float* Wx_f  = (const float*)d_in[3];
    const float* Wh_f  = (const float*)d_in[4];
    const float* b_f   = (const float*)d_in[5];
    const float* Wx_p  = (const float*)d_in[6];
    const float* Wh_p  = (const float*)d_in[7];
    const float* b_p   = (const float*)d_in[8];
    const float* Wx_s  = (const float*)d_in[9];
    const float* Wh_s  = (const float*)d_in[10];
    const float* b_s   = (const float*)d_in[11];
    const int*   fclk  = (const int*)d_in[12];
    const int*   pclk  = (const int*)d_in[13];
    const int*   sfreq = (const int*)d_in[14];
    float* out = (float*)d_out;

    dim3 grid(BATCH / 4);
    dim3 block(64);
    chive_kernel<<<grid, block>>>(frnn, phrnn, syl,
                                  Wx_f, Wh_f, b_f,
                                  Wx_p, Wh_p, b_p,
                                  Wx_s, Wh_s, b_s,
                                  fclk, pclk, sfreq, out);
}

// round 14
// speedup vs baseline: 1.9324x; 1.4473x over previous
#include <cuda_runtime.h>

#define T_STEPS 2048
#define BATCH   2048
#define HID     32
#define DF      8
#define DS      24

typedef unsigned long long ull;

// ---------- f32x2 packed helpers (sm_100+) ----------
__device__ __forceinline__ ull f2_fma(ull a, ull b, ull c) {
    ull d;
    asm("fma.rn.f32x2 %0, %1, %2, %3;" : "=l"(d) : "l"(a), "l"(b), "l"(c));
    return d;
}
__device__ __forceinline__ ull f2_add(ull a, ull b) {
    ull d;
    asm("add.rn.f32x2 %0, %1, %2;" : "=l"(d) : "l"(a), "l"(b));
    return d;
}
__device__ __forceinline__ ull f2_pack(float lo, float hi) {
    ull d;
    asm("mov.b64 %0, {%1, %2};" : "=l"(d) : "f"(lo), "f"(hi));
    return d;
}
__device__ __forceinline__ void f2_unpack(ull v, float &lo, float &hi) {
    asm("mov.b64 {%0, %1}, %2;" : "=f"(lo), "=f"(hi) : "l"(v));
}

// tanh(x) = sign(x) * (1 - e) / (1 + e), e = exp(-2|x|). ~1e-6 abs error.
__device__ __forceinline__ float fast_tanh(float x) {
    float ax = fabsf(x);
    float e  = __expf(-2.0f * ax);
    float r  = __fdividef(1.0f - e, 1.0f + e);
    return __int_as_float((__float_as_int(x) & 0x80000000) | __float_as_int(r));
}

__global__ __launch_bounds__(64)
void chive_kernel(const float* __restrict__ frnn, const float* __restrict__ phrnn,
                  const float* __restrict__ syl,
                  const float* __restrict__ Wx_f, const float* __restrict__ Wh_f,
                  const float* __restrict__ b_f,
                  const float* __restrict__ Wx_p, const float* __restrict__ Wh_p,
                  const float* __restrict__ b_p,
                  const float* __restrict__ Wx_s, const float* __restrict__ Wh_s,
                  const float* __restrict__ b_s,
                  const int* __restrict__ fclk, const int* __restrict__ pclk,
                  const int* __restrict__ sfreq,
                  float* __restrict__ out)
{
    __shared__ unsigned char sFlag[T_STEPS];
    // Per-warp broadcast arrays (float4-granular; read as ulonglong2 broadcasts)
    __shared__ __align__(16) float sIn [2][DF  * 4]; // (xf0,xp0,xf1,xp1)[j<8]
    __shared__ __align__(16) float sHfp[2][HID * 4]; // (hf0,hp0,hf1,hp1)[j]
    __shared__ __align__(16) float sQa [2][HID * 4]; // (hf0,hs0_0,hp0,hs1_0)[j]
    __shared__ __align__(16) float sQb [2][HID * 4]; // (hf1,hs0_1,hp1,hs1_1)[j]
    __shared__ __align__(16) float sQ2 [2][HID * 4]; // (xs0,hs2_0,xs1,hs2_1)[j]

    const int tid  = threadIdx.x;
    const int w    = tid >> 5;
    const int lane = tid & 31;
    const int b0   = (blockIdx.x * 2 + w) * 2;   // 2 elements per warp

    // ---- prologue: flags + zero-init of state arrays ----
    for (int t = tid; t < T_STEPS; t += 64) {
        unsigned f = 0u;
        if ((t % (fclk[t] + 1)) == 0) f |= 1u;
        if ((t % (pclk[t] + 1)) == 0) f |= 2u;
        if (sfreq[t] == 1)            f |= 4u;
        sFlag[t] = (unsigned char)f;
    }
    // zero: h0 = 0 AND the permanent x_s zero-pad in sQ2 (.x/.z for j>=24 are
    // never written again -- must be 0; learned the hard way in R9).
    *(float4*)&sHfp[w][lane * 4] = make_float4(0.f, 0.f, 0.f, 0.f);
    *(float4*)&sQ2 [w][lane * 4] = make_float4(0.f, 0.f, 0.f, 0.f);
    __syncthreads();

    // ---- register-resident weights: lane = output neuron ----
    ull wA[DF + HID];   // (Wx_f,Wx_p) rows then (Wh_f,Wh_p) rows
    ull wS[HID];        // (Wx_s, Wh_s) rows
    #pragma unroll
    for (int j = 0; j < DF; j++)
        wA[j] = f2_pack(Wx_f[j * HID + lane], Wx_p[j * HID + lane]);
    #pragma unroll
    for (int j = 0; j < HID; j++) {
        wA[DF + j] = f2_pack(Wh_f[j * HID + lane], Wh_p[j * HID + lane]);
        wS[j]      = f2_pack(Wx_s[j * HID + lane], Wh_s[j * HID + lane]);
    }
    const ull   biasfp = f2_pack(b_f[lane], b_p[lane]);
    const float bsl    = b_s[lane];

    float* In_  = sIn[w];
    float* Hfp_ = sHfp[w];
    float* Qa_  = sQa[w];
    float* Qb_  = sQb[w];
    float* Q2_  = sQ2[w];

    // ---- loader roles (identical to R5) ----
    int e = 0, chunk = 0;
    const float* baseP = 0;
    int strideT = 0;
    const bool loader = lane < 20;
    if (lane < 8) {
        e = (lane >> 1) & 1;
        chunk = lane & 1;
        baseP = ((lane < 4) ? frnn : phrnn) + (b0 + e) * DF + chunk * 4;
        strideT = BATCH * DF;
    } else if (lane < 20) {
        int r = lane - 8;
        e = r / 6;
        chunk = r - 6 * e;
        baseP = syl + (b0 + e) * DS + chunk * 4;
        strideT = BATCH * DS;
    }
    const int compA = e * 2 + ((lane >= 4 && lane < 8) ? 1 : 0);
    const int compS = e * 2;
    const int jb    = chunk * 4;

    // register state (this lane's neuron, both elements)
    float hf0 = 0.f, hp0 = 0.f, hs0_0 = 0.f, hs1_0 = 0.f, hs2_0 = 0.f;
    float hf1 = 0.f, hp1 = 0.f, hs0_1 = 0.f, hs1_1 = 0.f, hs2_1 = 0.f;

    float4 cur = loader ? *(const float4*)baseP : make_float4(0.f, 0.f, 0.f, 0.f);

    for (int t = 0; t < T_STEPS; t++) {
        float4 nxt = make_float4(0.f, 0.f, 0.f, 0.f);
        if (loader && t + 1 < T_STEPS)
            nxt = *(const float4*)(baseP + (size_t)(t + 1) * strideT);

        const unsigned fl = sFlag[t];

        // ================= phase A: f & p cells =================
        if (fl & 3u) {
            if (lane < 8) {
                In_[(jb + 0) * 4 + compA] = cur.x;
                In_[(jb + 1) * 4 + compA] = cur.y;
                In_[(jb + 2) * 4 + compA] = cur.z;
                In_[(jb + 3) * 4 + compA] = cur.w;
            }
            __syncwarp();

            ull a0A = biasfp, a0B = 0ull, a1A = biasfp, a1B = 0ull;
            #pragma unroll
            for (int j = 0; j < DF; j++) {
                ulonglong2 op = *(const ulonglong2*)&In_[j * 4]; // (xf0,xp0)(xf1,xp1)
                if (j & 1) { a0B = f2_fma(op.x, wA[j], a0B); a1B = f2_fma(op.y, wA[j], a1B); }
                else       { a0A = f2_fma(op.x, wA[j], a0A); a1A = f2_fma(op.y, wA[j], a1A); }
            }
            #pragma unroll
            for (int j = 0; j < HID; j++) {
                ulonglong2 op = *(const ulonglong2*)&Hfp_[j * 4]; // (hf0,hp0)(hf1,hp1)
                if (j & 1) { a0B = f2_fma(op.x, wA[DF + j], a0B); a1B = f2_fma(op.y, wA[DF + j], a1B); }
                else       { a0A = f2_fma(op.x, wA[DF + j], a0A); a1A = f2_fma(op.y, wA[DF + j], a1A); }
            }
            float af0, ap0, af1, ap1;
            f2_unpack(f2_add(a0A, a0B), af0, ap0);
            f2_unpack(f2_add(a1A, a1B), af1, ap1);
            if (fl & 1u) { hf0 = fast_tanh(af0); hf1 = fast_tanh(af1); }
            if (fl & 2u) { hp0 = fast_tanh(ap0); hp1 = fast_tanh(ap1); }
            __syncwarp();   // all lanes done reading old Hfp_
            *(float4*)&Hfp_[lane * 4] = make_float4(hf0, hp0, hf1, hp1);
        }

        // ================= phase B: syl cell (3 rows x 2 elems) =================
        if (fl & 4u) {
            __syncwarp();   // all lanes past previous B reads (also covers Hfp publish)
            *(float4*)&Qa_[lane * 4] = make_float4(hf0, hs0_0, hp0, hs1_0);
            *(float4*)&Qb_[lane * 4] = make_float4(hf1, hs0_1, hp1, hs1_1);
            Q2_[lane * 4 + 1] = hs2_0;
            Q2_[lane * 4 + 3] = hs2_1;
            if (lane >= 8 && lane < 20) {
                Q2_[(jb + 0) * 4 + compS] = cur.x;
                Q2_[(jb + 1) * 4 + compS] = cur.y;
                Q2_[(jb + 2) * 4 + compS] = cur.z;
                Q2_[(jb + 3) * 4 + compS] = cur.w;
            }
            __syncwarp();

            // accumulators: (x-stack part, Wh part) per row per element
            ull r00 = f2_pack(bsl, 0.f);
            ull r10 = r00, r20 = r00, r01 = r00, r11 = r00, r21 = r00;
            #pragma unroll
            for (int j = 0; j < HID; j++) {
                ull wv = wS[j];                                   // (Wx_s, Wh_s)
                ulonglong2 qa = *(const ulonglong2*)&Qa_[j * 4];  // (hf0,hs0_0)(hp0,hs1_0)
                ulonglong2 qb = *(const ulonglong2*)&Qb_[j * 4];
                ulonglong2 q2 = *(const ulonglong2*)&Q2_[j * 4];  // (xs0,hs2_0)(xs1,hs2_1)
                r00 = f2_fma(qa.x, wv, r00);
                r10 = f2_fma(qa.y, wv, r10);
                r01 = f2_fma(qb.x, wv, r01);
                r11 = f2_fma(qb.y, wv, r11);
                r20 = f2_fma(q2.x, wv, r20);
                r21 = f2_fma(q2.y, wv, r21);
            }
            float xa, ha;
            f2_unpack(r00, xa, ha); hs0_0 = fast_tanh(xa + ha);
            f2_unpack(r10, xa, ha); hs1_0 = fast_tanh(xa + ha);
            f2_unpack(r20, xa, ha); hs2_0 = fast_tanh(xa + ha);
            f2_unpack(r01, xa, ha); hs0_1 = fast_tanh(xa + ha);
            f2_unpack(r11, xa, ha); hs1_1 = fast_tanh(xa + ha);
            f2_unpack(r21, xa, ha); hs2_1 = fast_tanh(xa + ha);
        }

        cur = nxt;
    }

    // output h_s: [3, B, H]
    out[(0 * BATCH + b0    ) * HID + lane] = hs0_0;
    out[(1 * BATCH + b0    ) * HID + lane] = hs1_0;
    out[(2 * BATCH + b0    ) * HID + lane] = hs2_0;
    out[(0 * BATCH + b0 + 1) * HID + lane] = hs0_1;
    out[(1 * BATCH + b0 + 1) * HID + lane] = hs1_1;
    out[(2 * BATCH + b0 + 1) * HID + lane] = hs2_1;
}

extern "C" void kernel_launch(void* const* d_in, const int* in_sizes, int n_in,
                              void* d_out, int out_size) {
    const float* frnn  = (const float*)d_in[0];
    const float* phrnn = (const float*)d_in[1];
    const float* syl   = (const float*)d_in[2];
    const float* Wx_f  = (const float*)d_in[3];
    const float* Wh_f  = (const float*)d_in[4];
    const float* b_f   = (const float*)d_in[5];
    const float* Wx_p  = (const float*)d_in[6];
    const float* Wh_p  = (const float*)d_in[7];
    const float* b_p   = (const float*)d_in[8];
    const float* Wx_s  = (const float*)d_in[9];
    const float* Wh_s  = (const float*)d_in[10];
    const float* b_s   = (const float*)d_in[11];
    const int*   fclk  = (const int*)d_in[12];
    const int*   pclk  = (const int*)d_in[13];
    const int*   sfreq = (const int*)d_in[14];
    float* out = (float*)d_out;

    dim3 grid(BATCH / 4);   // 2 warps/CTA x 2 elements/warp
    dim3 block(64);
    chive_kernel<<<grid, block>>>(frnn, phrnn, syl,
                                  Wx_f, Wh_f, b_f,
                                  Wx_p, Wh_p, b_p,
                                  Wx_s, Wh_s, b_s,
                                  fclk, pclk, sfreq, out);
}